// round 2
// baseline (speedup 1.0000x reference)
#include <cuda_runtime.h>
#include <cstdint>

#define NB 32
#define NS 1024
#define NI 256
#define NH 512
#define NO 256

// Scratch: device globals (no allocations allowed)
__device__ float    g_inp_cur[(size_t)NB * NS * NH];     // 64 MB
__device__ unsigned g_spike_bits[(size_t)NB * NS * 16];  // 2 MB packed spikes

// ---------------------------------------------------------------------------
// K1: inp_cur[b*s, h] = X[b*s, i] @ Wi[i, h]   (fp32 SIMT tiled GEMM, at FMA peak)
// ---------------------------------------------------------------------------
__global__ __launch_bounds__(256) void k1_gemm(const float* __restrict__ X,
                                               const float* __restrict__ Wi) {
    __shared__ float As[64][33];
    __shared__ float Bs[32][64];
    const int m0 = blockIdx.y * 64, n0 = blockIdx.x * 64;
    const int tid = threadIdx.x;
    const int tm = tid >> 4, tn = tid & 15;

    float acc[4][4];
#pragma unroll
    for (int i = 0; i < 4; i++)
#pragma unroll
        for (int j = 0; j < 4; j++) acc[i][j] = 0.f;

    for (int k0 = 0; k0 < NI; k0 += 32) {
#pragma unroll
        for (int e = 0; e < 8; e++) {
            int idx = tid + e * 256;
            As[idx >> 5][idx & 31] = X[(size_t)(m0 + (idx >> 5)) * NI + k0 + (idx & 31)];
        }
#pragma unroll
        for (int e = 0; e < 8; e++) {
            int idx = tid + e * 256;
            Bs[idx >> 6][idx & 63] = Wi[(size_t)(k0 + (idx >> 6)) * NH + n0 + (idx & 63)];
        }
        __syncthreads();
#pragma unroll
        for (int k = 0; k < 32; k++) {
            float a[4];
#pragma unroll
            for (int i = 0; i < 4; i++) a[i] = As[tm * 4 + i][k];
            float4 bv = *reinterpret_cast<const float4*>(&Bs[k][tn * 4]);
            float b[4] = {bv.x, bv.y, bv.z, bv.w};
#pragma unroll
            for (int i = 0; i < 4; i++)
#pragma unroll
                for (int j = 0; j < 4; j++) acc[i][j] += a[i] * b[j];
        }
        __syncthreads();
    }
#pragma unroll
    for (int i = 0; i < 4; i++) {
        float4 v = make_float4(acc[i][0], acc[i][1], acc[i][2], acc[i][3]);
        *reinterpret_cast<float4*>(
            &g_inp_cur[(size_t)(m0 + tm * 4 + i) * NH + n0 + tn * 4]) = v;
    }
}

// ---------------------------------------------------------------------------
// helpers
// ---------------------------------------------------------------------------
__device__ __forceinline__ unsigned smem_u32(const void* p) {
    return (unsigned)__cvta_generic_to_shared(p);
}
__device__ __forceinline__ void cluster_sync_() {
    asm volatile("barrier.cluster.arrive.aligned;" ::: "memory");
    asm volatile("barrier.cluster.wait.aligned;" ::: "memory");
}
__device__ __forceinline__ void mbar_init(unsigned a, unsigned cnt) {
    asm volatile("mbarrier.init.shared.b64 [%0], %1;" :: "r"(a), "r"(cnt) : "memory");
}
// wait with cluster-scope acquire (remote producers)
__device__ __forceinline__ void mbar_wait_cluster(unsigned a, unsigned parity) {
    asm volatile(
        "{\n\t.reg .pred P;\n"
        "WL_%=:\n\t"
        "mbarrier.try_wait.parity.acquire.cluster.shared::cta.b64 P, [%0], %1, 0x989680;\n\t"
        "@P bra.uni WD_%=;\n\t"
        "bra.uni WL_%=;\n"
        "WD_%=:\n\t}"
        :: "r"(a), "r"(parity) : "memory");
}
// push 16B to peer smem + remote arrive (release at cluster scope)
__device__ __forceinline__ void push_masks(unsigned dst_laddr, unsigned mbar_laddr,
                                           unsigned rank, unsigned w0, unsigned w1,
                                           unsigned w2, unsigned w3) {
    asm volatile(
        "{\n\t.reg .b32 ra, rb;\n\t"
        "mapa.shared::cluster.u32 ra, %0, %2;\n\t"
        "st.shared::cluster.v4.b32 [ra], {%3,%4,%5,%6};\n\t"
        "mapa.shared::cluster.u32 rb, %1, %2;\n\t"
        "mbarrier.arrive.release.cluster.shared::cluster.b64 _, [rb];\n\t}"
        :: "r"(dst_laddr), "r"(mbar_laddr), "r"(rank),
           "r"(w0), "r"(w1), "r"(w2), "r"(w3) : "memory");
}
__device__ __forceinline__ void remote_arrive(unsigned mbar_laddr, unsigned rank) {
    asm volatile(
        "{\n\t.reg .b32 rb;\n\t"
        "mapa.shared::cluster.u32 rb, %0, %1;\n\t"
        "mbarrier.arrive.release.cluster.shared::cluster.b64 _, [rb];\n\t}"
        :: "r"(mbar_laddr), "r"(rank) : "memory");
}

// Warp-cooperative bit compaction (16 contiguous words -> ascending u16 list)
__device__ __forceinline__ int compact_warp(const unsigned* words, unsigned short* list) {
    const int lane = threadIdx.x & 31;
    unsigned w = words[lane >> 1];
    unsigned m = (lane & 1) ? (w >> 16) : (w & 0xFFFFu);
    int cnt = __popc(m);
    int sc = cnt;
#pragma unroll
    for (int d = 1; d < 32; d <<= 1) {
        int v = __shfl_up_sync(0xffffffffu, sc, d);
        if (lane >= d) sc += v;
    }
    int total = __shfl_sync(0xffffffffu, sc, 31);
    int off = sc - cnt;
    int base = (lane >> 1) * 32 + (lane & 1) * 16;
    while (m) {
        int j = __ffs(m) - 1;
        m &= m - 1;
        list[off++] = (unsigned short)(base + j);
    }
    return total;
}

// ---------------------------------------------------------------------------
// K2: persistent cluster scan. 16 clusters x 8 CTAs; cluster c owns batches
// {2c,2c+1}; rank r holds W_lat cols [64r,64r+64) in smem. Per step: mbarrier
// wait -> compact -> 8-wide prefetched sparse gather -> update -> ballot ->
// 16B DSMEM push + remote arrive to all 8 peers.
// smem layout (bytes):
//   0      : Wsm        512*64*4 = 131072
//   131072 : s_masks    [2 buf][8 rank][4 words] u32 = 256
//   131328 : s_list     [2][512] u16 = 2048
//   133376 : s_acc      [128] f32 = 512
//   133888 : s_cnt      [2] int = 8
//   133904 : mbar full  [2] u64 = 16
//   133920 : s_stage    [4] u32 = 16
// ---------------------------------------------------------------------------
#define SCAN_SMEM 133936

__global__ void __cluster_dims__(8, 1, 1) __launch_bounds__(256, 1)
k2_scan(const float* __restrict__ Wl, const float* __restrict__ thr) {
    extern __shared__ char smem[];
    float*          Wsm     = (float*)smem;
    unsigned*       s_masks = (unsigned*)(smem + 131072);
    unsigned short* s_list  = (unsigned short*)(smem + 131328);
    float*          s_acc   = (float*)(smem + 133376);
    int*            s_cnt   = (int*)(smem + 133888);
    unsigned long long* mbar = (unsigned long long*)(smem + 133904);
    unsigned*       s_stage = (unsigned*)(smem + 133920);

    const int tid  = threadIdx.x;
    const unsigned rank = blockIdx.x & 7;
    const int cid  = blockIdx.x >> 3;
    const int warp = tid >> 5;
    const int lane = tid & 31;

    // Load W_lat column slice [512 x 64]
    for (int idx = tid; idx < 512 * 64; idx += 256)
        Wsm[idx] = Wl[(size_t)(idx >> 6) * NH + rank * 64 + (idx & 63)];
    if (tid < 64) s_masks[tid] = 0u;  // zero both buffers (2*8*4 = 64 words)
    if (tid == 0) {
        mbar_init(smem_u32(&mbar[0]), 8);
        mbar_init(smem_u32(&mbar[1]), 8);
    }
    __syncthreads();
    cluster_sync_();  // all inits + zeros visible cluster-wide

    // Seed buffer 1 (consumed at t=0 with zero masks): one arrive per peer
    if (tid == 0) {
        const unsigned full1 = smem_u32(&mbar[1]);
#pragma unroll
        for (unsigned rk = 0; rk < 8; rk++) remote_arrive(full1, rk);
    }

    const int half = tid >> 7;        // block-parity of gather work
    const int b    = (tid >> 6) & 1;  // local batch
    const int col  = tid & 63;        // local neuron column
    float mp = 0.f;
    int refrac = 0;
    float th = 0.f;
    const float* icp = nullptr;
    if (tid < 128) {
        th  = thr[rank * 64 + col];
        icp = g_inp_cur + (size_t)(cid * 2 + b) * NS * NH + rank * 64 + col;
    }
    const unsigned masks_saddr = smem_u32(s_masks);
    const unsigned full0_addr = smem_u32(&mbar[0]);
    const unsigned full1_addr = smem_u32(&mbar[1]);
    const size_t bits_base = (size_t)(cid * 2) * NS * 16;
    unsigned ph0 = 0, ph1 = 0;

    for (int t = 0; t < NS; t++) {
        const int wbuf = t & 1, rbuf = wbuf ^ 1;
        float ic = 0.f;
        if (tid < 128) ic = icp[(size_t)t * NH];  // prefetch input current

        // One thread waits for all 8 peers' mask pushes of buffer rbuf
        if (tid == 0) {
            if (rbuf == 0) { mbar_wait_cluster(full0_addr, ph0); ph0 ^= 1; }
            else           { mbar_wait_cluster(full1_addr, ph1); ph1 ^= 1; }
        }
        __syncthreads();  // S1: masks visible to compaction warps

        // Compact spike masks (warp0: batch0, warp1: batch1)
        if (warp < 2) {
            const int bb = warp;
            const int widx = lane >> 1, sub = lane & 1;
            unsigned w32 = s_masks[rbuf * 32 + (widx >> 1) * 4 + bb * 2 + (widx & 1)];
            unsigned m = sub ? (w32 >> 16) : (w32 & 0xFFFFu);
            int cnt = __popc(m);
            int sc = cnt;
#pragma unroll
            for (int d = 1; d < 32; d <<= 1) {
                int v = __shfl_up_sync(0xffffffffu, sc, d);
                if (lane >= d) sc += v;
            }
            if (lane == 31) s_cnt[bb] = sc;
            int off = sc - cnt;
            int base = widx * 32 + sub * 16;
            unsigned short* L = &s_list[bb * 512];
            while (m) {
                int j = __ffs(m) - 1;
                m &= m - 1;
                L[off++] = (unsigned short)(base + j);
            }
        }
        __syncthreads();  // S2: list + counts ready

        // Sparse lateral gather: 8 indices per LDS.128, 8 independent weight LDS
        float part;
        {
            const int total = s_cnt[b];
            const int nblk = (total + 7) >> 3;
            const uint4* Lv = (const uint4*)&s_list[b * 512];
            float a0 = 0.f, a1 = 0.f, a2 = 0.f, a3 = 0.f;
            for (int j = half; j < nblk; j += 2) {
                uint4 v = Lv[j];
                unsigned id0 = v.x & 0xFFFFu, id1 = v.x >> 16;
                unsigned id2 = v.y & 0xFFFFu, id3 = v.y >> 16;
                unsigned id4 = v.z & 0xFFFFu, id5 = v.z >> 16;
                unsigned id6 = v.w & 0xFFFFu, id7 = v.w >> 16;
                int rem = total - j * 8;
                if (rem >= 8) {
                    a0 += Wsm[id0 * 64 + col];
                    a1 += Wsm[id1 * 64 + col];
                    a2 += Wsm[id2 * 64 + col];
                    a3 += Wsm[id3 * 64 + col];
                    a0 += Wsm[id4 * 64 + col];
                    a1 += Wsm[id5 * 64 + col];
                    a2 += Wsm[id6 * 64 + col];
                    a3 += Wsm[id7 * 64 + col];
                } else {
                    unsigned ids[8] = {id0, id1, id2, id3, id4, id5, id6, id7};
                    for (int k = 0; k < rem; k++) a0 += Wsm[ids[k] * 64 + col];
                }
            }
            part = (a0 + a1) + (a2 + a3);
        }
        if (tid >= 128) s_acc[tid & 127] = part;
        __syncthreads();  // S3: partner partial sums ready

        if (tid < 128) {
            float lat = part + s_acc[tid];
            float nmp = fmaf(0.95f, mp, ic) - lat;
            if (refrac > 0) nmp = 0.f;
            refrac = (refrac > 0) ? refrac - 1 : 0;
            bool sp = (nmp >= th);
            if (sp) { nmp = 0.f; refrac = 2; }
            mp = nmp;
            unsigned bal = __ballot_sync(0xffffffffu, sp);
            if (lane == 0) {
                const int wsub = warp & 1;
                g_spike_bits[bits_base + (size_t)b * NS * 16 + (size_t)t * 16 +
                             rank * 2 + wsub] = bal;
                s_stage[warp] = bal;  // order: {b0w0, b0w1, b1w0, b1w1}
            }
        }
        __syncthreads();  // S4: stage ready for pusher

        if (tid == 0) {
            unsigned w0 = s_stage[0], w1 = s_stage[1];
            unsigned w2 = s_stage[2], w3 = s_stage[3];
            unsigned dst = masks_saddr + (unsigned)(wbuf * 32 + rank * 4) * 4u;
            unsigned fb = wbuf ? full1_addr : full0_addr;
#pragma unroll
            for (unsigned rk = 0; rk < 8; rk++)
                push_masks(dst, fb, rk, w0, w1, w2, w3);
        }
    }
    cluster_sync_();  // keep smem alive for stragglers' in-flight remote stores
}

// ---------------------------------------------------------------------------
// K3: out[b*s, o] = spikes @ Wo, sparse from packed bits. 512 threads:
// 8 row-slots x 64 cols. Same 8-wide index prefetch as K2.
// ---------------------------------------------------------------------------
#define K3_SMEM (512 * 64 * 4 + 8 * 512 * 2)
#define K3_ROWS_PER_CTA 222

__global__ __launch_bounds__(512, 1) void k3_out(const float* __restrict__ Wo,
                                                 float* __restrict__ out) {
    extern __shared__ char smem[];
    float*          Ws    = (float*)smem;                            // 512 x 64
    unsigned short* lists = (unsigned short*)(smem + 512 * 64 * 4);  // [8][512]
    __shared__ int cnts[8];

    const int tid = threadIdx.x;
    const int g = (int)blockIdx.y, chunk = (int)blockIdx.x;
    const int rs = tid >> 6, col = tid & 63;

    for (int idx = tid; idx < 512 * 64; idx += 512)
        Ws[idx] = Wo[(size_t)(idx >> 6) * NO + g * 64 + (idx & 63)];
    __syncthreads();

    const int r0 = chunk * K3_ROWS_PER_CTA;
    const int r1 = min(r0 + K3_ROWS_PER_CTA, NB * NS);
    for (int rb = r0; rb < r1; rb += 8) {
        const int r = rb + rs;
        const bool valid = (r < r1);
        if (((tid >> 5) & 1) == 0 && valid) {
            int total = compact_warp(&g_spike_bits[(size_t)r * 16], &lists[rs * 512]);
            if ((tid & 31) == 0) cnts[rs] = total;
        }
        __syncthreads();
        if (valid) {
            const int n = cnts[rs];
            const int nblk = (n + 7) >> 3;
            const uint4* Lv = (const uint4*)&lists[rs * 512];
            float a0 = 0.f, a1 = 0.f, a2 = 0.f, a3 = 0.f;
            for (int j = 0; j < nblk; j++) {
                uint4 v = Lv[j];
                unsigned id0 = v.x & 0xFFFFu, id1 = v.x >> 16;
                unsigned id2 = v.y & 0xFFFFu, id3 = v.y >> 16;
                unsigned id4 = v.z & 0xFFFFu, id5 = v.z >> 16;
                unsigned id6 = v.w & 0xFFFFu, id7 = v.w >> 16;
                int rem = n - j * 8;
                if (rem >= 8) {
                    a0 += Ws[id0 * 64 + col];
                    a1 += Ws[id1 * 64 + col];
                    a2 += Ws[id2 * 64 + col];
                    a3 += Ws[id3 * 64 + col];
                    a0 += Ws[id4 * 64 + col];
                    a1 += Ws[id5 * 64 + col];
                    a2 += Ws[id6 * 64 + col];
                    a3 += Ws[id7 * 64 + col];
                } else {
                    unsigned ids[8] = {id0, id1, id2, id3, id4, id5, id6, id7};
                    for (int k = 0; k < rem; k++) a0 += Ws[ids[k] * 64 + col];
                }
            }
            out[(size_t)r * NO + g * 64 + col] = (a0 + a1) + (a2 + a3);
        }
        __syncthreads();
    }
}

// ---------------------------------------------------------------------------
extern "C" void kernel_launch(void* const* d_in, const int* in_sizes, int n_in,
                              void* d_out, int out_size) {
    const float* x  = (const float*)d_in[0];
    const float* wi = (const float*)d_in[1];
    const float* wl = (const float*)d_in[2];
    const float* wo = (const float*)d_in[3];
    const float* th = (const float*)d_in[4];
    float* out = (float*)d_out;

    cudaFuncSetAttribute(k2_scan, cudaFuncAttributeMaxDynamicSharedMemorySize, SCAN_SMEM);
    cudaFuncSetAttribute(k3_out, cudaFuncAttributeMaxDynamicSharedMemorySize, K3_SMEM);

    dim3 g1(NH / 64, (NB * NS) / 64);
    k1_gemm<<<g1, 256>>>(x, wi);
    k2_scan<<<128, 256, SCAN_SMEM>>>(wl, th);
    dim3 g3((NB * NS + K3_ROWS_PER_CTA - 1) / K3_ROWS_PER_CTA, NO / 64);
    k3_out<<<g3, 512, K3_SMEM>>>(wo, out);
}

// round 3
// speedup vs baseline: 1.6543x; 1.6543x over previous
#include <cuda_runtime.h>
#include <cstdint>

#define NB 32
#define NS 1024
#define NI 256
#define NH 512
#define NO 256

// Scratch: device globals (no allocations allowed)
__device__ float    g_inp_cur[(size_t)NB * NS * NH];     // 64 MB
__device__ unsigned g_spike_bits[(size_t)NB * NS * 16];  // 2 MB packed spikes

// ---------------------------------------------------------------------------
// K1: inp_cur[b*s, h] = X[b*s, i] @ Wi[i, h]   (fp32 SIMT tiled GEMM, at FMA peak)
// ---------------------------------------------------------------------------
__global__ __launch_bounds__(256) void k1_gemm(const float* __restrict__ X,
                                               const float* __restrict__ Wi) {
    __shared__ float As[64][33];
    __shared__ float Bs[32][64];
    const int m0 = blockIdx.y * 64, n0 = blockIdx.x * 64;
    const int tid = threadIdx.x;
    const int tm = tid >> 4, tn = tid & 15;

    float acc[4][4];
#pragma unroll
    for (int i = 0; i < 4; i++)
#pragma unroll
        for (int j = 0; j < 4; j++) acc[i][j] = 0.f;

    for (int k0 = 0; k0 < NI; k0 += 32) {
#pragma unroll
        for (int e = 0; e < 8; e++) {
            int idx = tid + e * 256;
            As[idx >> 5][idx & 31] = X[(size_t)(m0 + (idx >> 5)) * NI + k0 + (idx & 31)];
        }
#pragma unroll
        for (int e = 0; e < 8; e++) {
            int idx = tid + e * 256;
            Bs[idx >> 6][idx & 63] = Wi[(size_t)(k0 + (idx >> 6)) * NH + n0 + (idx & 63)];
        }
        __syncthreads();
#pragma unroll
        for (int k = 0; k < 32; k++) {
            float a[4];
#pragma unroll
            for (int i = 0; i < 4; i++) a[i] = As[tm * 4 + i][k];
            float4 bv = *reinterpret_cast<const float4*>(&Bs[k][tn * 4]);
            float b[4] = {bv.x, bv.y, bv.z, bv.w};
#pragma unroll
            for (int i = 0; i < 4; i++)
#pragma unroll
                for (int j = 0; j < 4; j++) acc[i][j] += a[i] * b[j];
        }
        __syncthreads();
    }
#pragma unroll
    for (int i = 0; i < 4; i++) {
        float4 v = make_float4(acc[i][0], acc[i][1], acc[i][2], acc[i][3]);
        *reinterpret_cast<float4*>(
            &g_inp_cur[(size_t)(m0 + tm * 4 + i) * NH + n0 + tn * 4]) = v;
    }
}

// ---------------------------------------------------------------------------
// helpers
// ---------------------------------------------------------------------------
__device__ __forceinline__ unsigned smem_u32(const void* p) {
    return (unsigned)__cvta_generic_to_shared(p);
}
__device__ __forceinline__ void st_cluster_u32(unsigned laddr, unsigned rank, unsigned val) {
    asm volatile(
        "{\n\t.reg .b32 ra;\n\t"
        "mapa.shared::cluster.u32 ra, %0, %1;\n\t"
        "st.shared::cluster.u32 [ra], %2;\n\t}"
        :: "r"(laddr), "r"(rank), "r"(val) : "memory");
}
__device__ __forceinline__ void cluster_sync_() {
    asm volatile("barrier.cluster.arrive.aligned;" ::: "memory");
    asm volatile("barrier.cluster.wait.aligned;" ::: "memory");
}

// Warp-cooperative bit compaction (16 contiguous words -> ascending u16 list)
__device__ __forceinline__ int compact_warp(const unsigned* words, unsigned short* list) {
    const int lane = threadIdx.x & 31;
    unsigned w = words[lane >> 1];
    unsigned m = (lane & 1) ? (w >> 16) : (w & 0xFFFFu);
    int cnt = __popc(m);
    int sc = cnt;
#pragma unroll
    for (int d = 1; d < 32; d <<= 1) {
        int v = __shfl_up_sync(0xffffffffu, sc, d);
        if (lane >= d) sc += v;
    }
    int total = __shfl_sync(0xffffffffu, sc, 31);
    int off = sc - cnt;
    int base = (lane >> 1) * 32 + (lane & 1) * 16;
    while (m) {
        int j = __ffs(m) - 1;
        m &= m - 1;
        list[off++] = (unsigned short)(base + j);
    }
    return total;
}

// ---------------------------------------------------------------------------
// K2: persistent cluster scan (round-1 proven comm protocol + 8-wide gather).
// 16 clusters x 8 CTAs. Cluster c owns batches {2c, 2c+1}. CTA rank r holds
// W_lat columns [64r, 64r+64) in smem (128 KB). Per step: compact spike masks
// -> 8-wide prefetched sparse column sums -> membrane update -> ballot ->
// push 64 bits to all 8 peers (plain DSMEM stores) -> cluster barrier.
// smem layout (bytes):
//   0      : Wsm     512*64*4 = 131072
//   131072 : s_masks [2 buf][2 b][16 words] u32 = 256
//   131328 : s_list  [2][512] u16 = 2048   (16B aligned)
//   133376 : s_acc   [128] f32 = 512
//   133888 : s_cnt   [2] int = 8
// ---------------------------------------------------------------------------
#define SCAN_SMEM (131072 + 256 + 2048 + 512 + 16)

__global__ void __cluster_dims__(8, 1, 1) __launch_bounds__(256, 1)
k2_scan(const float* __restrict__ Wl, const float* __restrict__ thr) {
    extern __shared__ char smem[];
    float*          Wsm     = (float*)smem;
    unsigned*       s_masks = (unsigned*)(smem + 131072);
    unsigned short* s_list  = (unsigned short*)(smem + 131328);
    float*          s_acc   = (float*)(smem + 133376);
    int*            s_cnt   = (int*)(smem + 133888);

    const int tid  = threadIdx.x;
    const unsigned rank = blockIdx.x & 7;
    const int cid  = blockIdx.x >> 3;
    const int warp = tid >> 5;
    const int lane = tid & 31;

    // Load W_lat column slice [512 rows x 64 cols]
    for (int idx = tid; idx < 512 * 64; idx += 256)
        Wsm[idx] = Wl[(size_t)(idx >> 6) * NH + rank * 64 + (idx & 63)];
    if (tid < 64) s_masks[tid] = 0u;  // zero both buffers

    const int half = tid >> 7;        // which half of the spike list
    const int b    = (tid >> 6) & 1;  // local batch
    const int col  = tid & 63;        // local neuron column

    float mp = 0.f;
    int refrac = 0;
    float th = 0.f;
    const float* icp = nullptr;
    if (tid < 128) {
        th  = thr[rank * 64 + col];
        icp = g_inp_cur + (size_t)(cid * 2 + b) * NS * NH + rank * 64 + col;
    }
    const unsigned masks_saddr = smem_u32(s_masks);
    const size_t bits_base = (size_t)(cid * 2) * NS * 16;

    cluster_sync_();  // all CTAs initialized before any remote pushes / reads

    for (int t = 0; t < NS; t++) {
        const int wbuf = t & 1, rbuf = wbuf ^ 1;
        float ic = 0.f;
        if (tid < 128) ic = icp[(size_t)t * NH];  // prefetch input current

        // Compact previous-step spike masks (warp0: batch0, warp1: batch1)
        if (warp < 2) {
            int total = compact_warp(&s_masks[(rbuf * 2 + warp) * 16], &s_list[warp * 512]);
            if (lane == 0) s_cnt[warp] = total;
        }
        __syncthreads();  // list + counts ready

        // Sparse lateral gather: 8 packed indices per LDS.128, 8 independent
        // weight LDS into 4 accumulators (breaks the serial LDS chain)
        float part;
        {
            const int total = s_cnt[b];
            const int nblk = (total + 7) >> 3;
            const uint4* Lv = (const uint4*)&s_list[b * 512];
            float a0 = 0.f, a1 = 0.f, a2 = 0.f, a3 = 0.f;
            for (int j = half; j < nblk; j += 2) {
                uint4 v = Lv[j];
                unsigned id0 = v.x & 0xFFFFu, id1 = v.x >> 16;
                unsigned id2 = v.y & 0xFFFFu, id3 = v.y >> 16;
                unsigned id4 = v.z & 0xFFFFu, id5 = v.z >> 16;
                unsigned id6 = v.w & 0xFFFFu, id7 = v.w >> 16;
                int rem = total - j * 8;
                if (rem >= 8) {
                    a0 += Wsm[id0 * 64 + col];
                    a1 += Wsm[id1 * 64 + col];
                    a2 += Wsm[id2 * 64 + col];
                    a3 += Wsm[id3 * 64 + col];
                    a0 += Wsm[id4 * 64 + col];
                    a1 += Wsm[id5 * 64 + col];
                    a2 += Wsm[id6 * 64 + col];
                    a3 += Wsm[id7 * 64 + col];
                } else {
                    unsigned ids[8] = {id0, id1, id2, id3, id4, id5, id6, id7};
                    for (int k = 0; k < rem; k++) a0 += Wsm[ids[k] * 64 + col];
                }
            }
            part = (a0 + a1) + (a2 + a3);
        }
        if (tid >= 128) s_acc[tid & 127] = part;
        __syncthreads();  // partner partial sums ready

        if (tid < 128) {
            float lat = part + s_acc[tid];
            float nmp = fmaf(0.95f, mp, ic) - lat;
            if (refrac > 0) nmp = 0.f;
            refrac = (refrac > 0) ? refrac - 1 : 0;
            bool sp = (nmp >= th);
            if (sp) { nmp = 0.f; refrac = 2; }
            mp = nmp;
            unsigned bal = __ballot_sync(0xffffffffu, sp);
            if (lane == 0) {
                const int wsub = warp & 1;  // low/high 32 cols of my 64
                g_spike_bits[bits_base + (size_t)b * NS * 16 + (size_t)t * 16 +
                             rank * 2 + wsub] = bal;
                unsigned la = masks_saddr +
                              ((unsigned)(wbuf * 2 + b) * 16 + rank * 2 + wsub) * 4u;
#pragma unroll
                for (unsigned rk = 0; rk < 8; rk++) st_cluster_u32(la, rk, bal);
            }
        }
        cluster_sync_();  // release my pushes, acquire peers' pushes
    }
}

// ---------------------------------------------------------------------------
// K3: out[b*s, o] = spikes @ Wo, sparse from packed bits. 512 threads:
// 8 row-slots x 64 cols, 8-wide prefetched gather.
// ---------------------------------------------------------------------------
#define K3_SMEM (512 * 64 * 4 + 8 * 512 * 2)
#define K3_ROWS_PER_CTA 222

__global__ __launch_bounds__(512, 1) void k3_out(const float* __restrict__ Wo,
                                                 float* __restrict__ out) {
    extern __shared__ char smem[];
    float*          Ws    = (float*)smem;                            // 512 x 64
    unsigned short* lists = (unsigned short*)(smem + 512 * 64 * 4);  // [8][512]
    __shared__ int cnts[8];

    const int tid = threadIdx.x;
    const int g = (int)blockIdx.y, chunk = (int)blockIdx.x;
    const int rs = tid >> 6, col = tid & 63;

    for (int idx = tid; idx < 512 * 64; idx += 512)
        Ws[idx] = Wo[(size_t)(idx >> 6) * NO + g * 64 + (idx & 63)];
    __syncthreads();

    const int r0 = chunk * K3_ROWS_PER_CTA;
    const int r1 = min(r0 + K3_ROWS_PER_CTA, NB * NS);
    for (int rb = r0; rb < r1; rb += 8) {
        const int r = rb + rs;
        const bool valid = (r < r1);
        if (((tid >> 5) & 1) == 0 && valid) {
            int total = compact_warp(&g_spike_bits[(size_t)r * 16], &lists[rs * 512]);
            if ((tid & 31) == 0) cnts[rs] = total;
        }
        __syncthreads();
        if (valid) {
            const int n = cnts[rs];
            const int nblk = (n + 7) >> 3;
            const uint4* Lv = (const uint4*)&lists[rs * 512];
            float a0 = 0.f, a1 = 0.f, a2 = 0.f, a3 = 0.f;
            for (int j = 0; j < nblk; j++) {
                uint4 v = Lv[j];
                unsigned id0 = v.x & 0xFFFFu, id1 = v.x >> 16;
                unsigned id2 = v.y & 0xFFFFu, id3 = v.y >> 16;
                unsigned id4 = v.z & 0xFFFFu, id5 = v.z >> 16;
                unsigned id6 = v.w & 0xFFFFu, id7 = v.w >> 16;
                int rem = n - j * 8;
                if (rem >= 8) {
                    a0 += Ws[id0 * 64 + col];
                    a1 += Ws[id1 * 64 + col];
                    a2 += Ws[id2 * 64 + col];
                    a3 += Ws[id3 * 64 + col];
                    a0 += Ws[id4 * 64 + col];
                    a1 += Ws[id5 * 64 + col];
                    a2 += Ws[id6 * 64 + col];
                    a3 += Ws[id7 * 64 + col];
                } else {
                    unsigned ids[8] = {id0, id1, id2, id3, id4, id5, id6, id7};
                    for (int k = 0; k < rem; k++) a0 += Ws[ids[k] * 64 + col];
                }
            }
            out[(size_t)r * NO + g * 64 + col] = (a0 + a1) + (a2 + a3);
        }
        __syncthreads();
    }
}

// ---------------------------------------------------------------------------
extern "C" void kernel_launch(void* const* d_in, const int* in_sizes, int n_in,
                              void* d_out, int out_size) {
    const float* x  = (const float*)d_in[0];
    const float* wi = (const float*)d_in[1];
    const float* wl = (const float*)d_in[2];
    const float* wo = (const float*)d_in[3];
    const float* th = (const float*)d_in[4];
    float* out = (float*)d_out;

    cudaFuncSetAttribute(k2_scan, cudaFuncAttributeMaxDynamicSharedMemorySize, SCAN_SMEM);
    cudaFuncSetAttribute(k3_out, cudaFuncAttributeMaxDynamicSharedMemorySize, K3_SMEM);

    dim3 g1(NH / 64, (NB * NS) / 64);
    k1_gemm<<<g1, 256>>>(x, wi);
    k2_scan<<<128, 256, SCAN_SMEM>>>(wl, th);
    dim3 g3((NB * NS + K3_ROWS_PER_CTA - 1) / K3_ROWS_PER_CTA, NO / 64);
    k3_out<<<g3, 512, K3_SMEM>>>(wo, out);
}

// round 4
// speedup vs baseline: 2.9065x; 1.7569x over previous
#include <cuda_runtime.h>
#include <cstdint>

#define NB 32
#define NS 1024
#define NI 256
#define NH 512
#define NO 256

// Scratch: device globals (no allocations allowed)
__device__ float    g_inp_cur[(size_t)NB * NS * NH];     // 64 MB
__device__ unsigned g_spike_bits[(size_t)NB * NS * 16];  // 2 MB packed spikes

// ---------------------------------------------------------------------------
// K1: inp_cur[b*s, h] = X[b*s, i] @ Wi[i, h]   (fp32 SIMT tiled GEMM, at FMA peak)
// ---------------------------------------------------------------------------
__global__ __launch_bounds__(256) void k1_gemm(const float* __restrict__ X,
                                               const float* __restrict__ Wi) {
    __shared__ float As[64][33];
    __shared__ float Bs[32][64];
    const int m0 = blockIdx.y * 64, n0 = blockIdx.x * 64;
    const int tid = threadIdx.x;
    const int tm = tid >> 4, tn = tid & 15;

    float acc[4][4];
#pragma unroll
    for (int i = 0; i < 4; i++)
#pragma unroll
        for (int j = 0; j < 4; j++) acc[i][j] = 0.f;

    for (int k0 = 0; k0 < NI; k0 += 32) {
#pragma unroll
        for (int e = 0; e < 8; e++) {
            int idx = tid + e * 256;
            As[idx >> 5][idx & 31] = X[(size_t)(m0 + (idx >> 5)) * NI + k0 + (idx & 31)];
        }
#pragma unroll
        for (int e = 0; e < 8; e++) {
            int idx = tid + e * 256;
            Bs[idx >> 6][idx & 63] = Wi[(size_t)(k0 + (idx >> 6)) * NH + n0 + (idx & 63)];
        }
        __syncthreads();
#pragma unroll
        for (int k = 0; k < 32; k++) {
            float a[4];
#pragma unroll
            for (int i = 0; i < 4; i++) a[i] = As[tm * 4 + i][k];
            float4 bv = *reinterpret_cast<const float4*>(&Bs[k][tn * 4]);
            float b[4] = {bv.x, bv.y, bv.z, bv.w};
#pragma unroll
            for (int i = 0; i < 4; i++)
#pragma unroll
                for (int j = 0; j < 4; j++) acc[i][j] += a[i] * b[j];
        }
        __syncthreads();
    }
#pragma unroll
    for (int i = 0; i < 4; i++) {
        float4 v = make_float4(acc[i][0], acc[i][1], acc[i][2], acc[i][3]);
        *reinterpret_cast<float4*>(
            &g_inp_cur[(size_t)(m0 + tm * 4 + i) * NH + n0 + tn * 4]) = v;
    }
}

// ---------------------------------------------------------------------------
// Warp-cooperative bit compaction (16 contiguous words = 512 bits -> ascending
// u16 index list). lane l handles 16-bit half (l&1) of word (l>>1).
// ---------------------------------------------------------------------------
__device__ __forceinline__ int compact_warp(const unsigned* words, unsigned short* list) {
    const int lane = threadIdx.x & 31;
    unsigned w = words[lane >> 1];
    unsigned m = (lane & 1) ? (w >> 16) : (w & 0xFFFFu);
    int cnt = __popc(m);
    int sc = cnt;
#pragma unroll
    for (int d = 1; d < 32; d <<= 1) {
        int v = __shfl_up_sync(0xffffffffu, sc, d);
        if (lane >= d) sc += v;
    }
    int total = __shfl_sync(0xffffffffu, sc, 31);
    int off = sc - cnt;
    int base = (lane >> 1) * 32 + (lane & 1) * 16;
    while (m) {
        int j = __ffs(m) - 1;
        m &= m - 1;
        list[off++] = (unsigned short)(base + j);
    }
    return total;
}

// ---------------------------------------------------------------------------
// K2: one CTA per batch (32 CTAs x 512 threads). NO clusters, NO DSMEM.
// Thread j owns neuron j (mp/refrac in registers). Per step:
//   warp0 compacts prev-step 512-bit mask -> list ; barrier
//   4 teams of 128 threads gather W_lat rows from L2 via coalesced LDG.128
//   (thread covers cols 4c..4c+3), partials to smem ; barrier
//   thread j reduces 4 partials, membrane update, ballot -> masks + gmem bits
//   barrier.
// Per-step floor: ~n_active*2KB / 128B/cyc L1tex = ~2k cyc; everything local.
// ---------------------------------------------------------------------------
__global__ __launch_bounds__(512, 1) void k2_scan(const float* __restrict__ Wl,
                                                  const float* __restrict__ thr) {
    __shared__ unsigned s_masks[2][16];                    // double-buffered spike bits
    __shared__ __align__(16) unsigned short s_list[512];   // active indices
    __shared__ float s_part[4 * 512];                      // team partial laterals
    __shared__ int s_cnt;

    const int tid  = threadIdx.x;
    const int b    = blockIdx.x;
    const int warp = tid >> 5, lane = tid & 31;
    const int team = tid >> 7, c = tid & 127;   // team 0..3, col group 4c..4c+3

    if (tid < 32) ((unsigned*)s_masks)[tid] = 0u;  // zero both buffers

    float mp = 0.f;
    int refrac = 0;
    const float th = thr[tid];
    const float* icp = g_inp_cur + (size_t)b * NS * NH + tid;
    const float* Wcol = Wl + 4 * c;  // + i*NH indexes row i, cols 4c..4c+3
    const size_t bits_base = (size_t)b * NS * 16;

    __syncthreads();

    for (int t = 0; t < NS; t++) {
        const int wbuf = t & 1, rbuf = wbuf ^ 1;  // t=0 reads buf1 (zeros)
        const float ic = icp[(size_t)t * NH];     // issued early, used ~2k cyc later

        if (warp == 0) {
            int total = compact_warp(s_masks[rbuf], s_list);
            if (lane == 0) s_cnt = total;
        }
        __syncthreads();  // B1: list + count ready

        // Team-chunked sparse gather from L2 (coalesced LDG.128 per row)
        const int cnt = s_cnt;
        const int chunk = ((cnt + 31) >> 5) << 3;  // per-team, multiple of 8
        const int e0 = team * chunk;
        const int e1 = min(e0 + chunk, cnt);
        float4 accA = make_float4(0.f, 0.f, 0.f, 0.f);
        float4 accB = make_float4(0.f, 0.f, 0.f, 0.f);
        for (int blk = e0; blk < e1; blk += 8) {
            uint4 v = *reinterpret_cast<const uint4*>(&s_list[blk]);  // 8 indices
            unsigned id0 = v.x & 0xFFFFu, id1 = v.x >> 16;
            unsigned id2 = v.y & 0xFFFFu, id3 = v.y >> 16;
            unsigned id4 = v.z & 0xFFFFu, id5 = v.z >> 16;
            unsigned id6 = v.w & 0xFFFFu, id7 = v.w >> 16;
            if (e1 - blk >= 8) {
                float4 w0 = *reinterpret_cast<const float4*>(&Wcol[id0 * NH]);
                float4 w1 = *reinterpret_cast<const float4*>(&Wcol[id1 * NH]);
                float4 w2 = *reinterpret_cast<const float4*>(&Wcol[id2 * NH]);
                float4 w3 = *reinterpret_cast<const float4*>(&Wcol[id3 * NH]);
                float4 w4 = *reinterpret_cast<const float4*>(&Wcol[id4 * NH]);
                float4 w5 = *reinterpret_cast<const float4*>(&Wcol[id5 * NH]);
                float4 w6 = *reinterpret_cast<const float4*>(&Wcol[id6 * NH]);
                float4 w7 = *reinterpret_cast<const float4*>(&Wcol[id7 * NH]);
                accA.x += w0.x; accA.y += w0.y; accA.z += w0.z; accA.w += w0.w;
                accB.x += w1.x; accB.y += w1.y; accB.z += w1.z; accB.w += w1.w;
                accA.x += w2.x; accA.y += w2.y; accA.z += w2.z; accA.w += w2.w;
                accB.x += w3.x; accB.y += w3.y; accB.z += w3.z; accB.w += w3.w;
                accA.x += w4.x; accA.y += w4.y; accA.z += w4.z; accA.w += w4.w;
                accB.x += w5.x; accB.y += w5.y; accB.z += w5.z; accB.w += w5.w;
                accA.x += w6.x; accA.y += w6.y; accA.z += w6.z; accA.w += w6.w;
                accB.x += w7.x; accB.y += w7.y; accB.z += w7.z; accB.w += w7.w;
            } else {
                unsigned ids[8] = {id0, id1, id2, id3, id4, id5, id6, id7};
                int rem = e1 - blk;
                for (int k = 0; k < rem; k++) {
                    float4 w = *reinterpret_cast<const float4*>(&Wcol[ids[k] * NH]);
                    accA.x += w.x; accA.y += w.y; accA.z += w.z; accA.w += w.w;
                }
            }
        }
        accA.x += accB.x; accA.y += accB.y; accA.z += accB.z; accA.w += accB.w;
        *reinterpret_cast<float4*>(&s_part[team * 512 + 4 * c]) = accA;
        __syncthreads();  // B2: partials ready

        // Reduce 4 team partials, membrane update for neuron j = tid
        float lat = (s_part[tid] + s_part[512 + tid]) +
                    (s_part[1024 + tid] + s_part[1536 + tid]);
        float nmp = fmaf(0.95f, mp, ic) - lat;
        if (refrac > 0) nmp = 0.f;
        refrac = (refrac > 0) ? refrac - 1 : 0;
        bool sp = (nmp >= th);
        if (sp) { nmp = 0.f; refrac = 2; }
        mp = nmp;
        unsigned bal = __ballot_sync(0xffffffffu, sp);
        if (lane == 0) {
            s_masks[wbuf][warp] = bal;
            g_spike_bits[bits_base + (size_t)t * 16 + warp] = bal;
        }
        __syncthreads();  // B3: masks ready for next step's compact
    }
}

// ---------------------------------------------------------------------------
// K3: out[b*s, o] = spikes @ Wo, sparse from packed bits. 512 threads:
// 8 row-slots x 64 cols, 8-wide prefetched gather from smem-resident Wo slice.
// ---------------------------------------------------------------------------
#define K3_SMEM (512 * 64 * 4 + 8 * 512 * 2)
#define K3_ROWS_PER_CTA 222

__global__ __launch_bounds__(512, 1) void k3_out(const float* __restrict__ Wo,
                                                 float* __restrict__ out) {
    extern __shared__ char smem[];
    float*          Ws    = (float*)smem;                            // 512 x 64
    unsigned short* lists = (unsigned short*)(smem + 512 * 64 * 4);  // [8][512]
    __shared__ int cnts[8];

    const int tid = threadIdx.x;
    const int g = (int)blockIdx.y, chunk = (int)blockIdx.x;
    const int rs = tid >> 6, col = tid & 63;

    for (int idx = tid; idx < 512 * 64; idx += 512)
        Ws[idx] = Wo[(size_t)(idx >> 6) * NO + g * 64 + (idx & 63)];
    __syncthreads();

    const int r0 = chunk * K3_ROWS_PER_CTA;
    const int r1 = min(r0 + K3_ROWS_PER_CTA, NB * NS);
    for (int rb = r0; rb < r1; rb += 8) {
        const int r = rb + rs;
        const bool valid = (r < r1);
        if (((tid >> 5) & 1) == 0 && valid) {
            int total = compact_warp(&g_spike_bits[(size_t)r * 16], &lists[rs * 512]);
            if ((tid & 31) == 0) cnts[rs] = total;
        }
        __syncthreads();
        if (valid) {
            const int n = cnts[rs];
            const int nblk = (n + 7) >> 3;
            const uint4* Lv = (const uint4*)&lists[rs * 512];
            float a0 = 0.f, a1 = 0.f, a2 = 0.f, a3 = 0.f;
            for (int j = 0; j < nblk; j++) {
                uint4 v = Lv[j];
                unsigned id0 = v.x & 0xFFFFu, id1 = v.x >> 16;
                unsigned id2 = v.y & 0xFFFFu, id3 = v.y >> 16;
                unsigned id4 = v.z & 0xFFFFu, id5 = v.z >> 16;
                unsigned id6 = v.w & 0xFFFFu, id7 = v.w >> 16;
                int rem = n - j * 8;
                if (rem >= 8) {
                    a0 += Ws[id0 * 64 + col];
                    a1 += Ws[id1 * 64 + col];
                    a2 += Ws[id2 * 64 + col];
                    a3 += Ws[id3 * 64 + col];
                    a0 += Ws[id4 * 64 + col];
                    a1 += Ws[id5 * 64 + col];
                    a2 += Ws[id6 * 64 + col];
                    a3 += Ws[id7 * 64 + col];
                } else {
                    unsigned ids[8] = {id0, id1, id2, id3, id4, id5, id6, id7};
                    for (int k = 0; k < rem; k++) a0 += Ws[ids[k] * 64 + col];
                }
            }
            out[(size_t)r * NO + g * 64 + col] = (a0 + a1) + (a2 + a3);
        }
        __syncthreads();
    }
}

// ---------------------------------------------------------------------------
extern "C" void kernel_launch(void* const* d_in, const int* in_sizes, int n_in,
                              void* d_out, int out_size) {
    const float* x  = (const float*)d_in[0];
    const float* wi = (const float*)d_in[1];
    const float* wl = (const float*)d_in[2];
    const float* wo = (const float*)d_in[3];
    const float* th = (const float*)d_in[4];
    float* out = (float*)d_out;

    cudaFuncSetAttribute(k3_out, cudaFuncAttributeMaxDynamicSharedMemorySize, K3_SMEM);

    dim3 g1(NH / 64, (NB * NS) / 64);
    k1_gemm<<<g1, 256>>>(x, wi);
    k2_scan<<<NB, 512>>>(wl, th);
    dim3 g3((NB * NS + K3_ROWS_PER_CTA - 1) / K3_ROWS_PER_CTA, NO / 64);
    k3_out<<<g3, 512, K3_SMEM>>>(wo, out);
}